// round 14
// baseline (speedup 1.0000x reference)
#include <cuda_runtime.h>
#include <cstdint>

#define N_NODES 100000
#define N_EDGES 600000
#define CH 128
#define NF (N_NODES * CH)

// ---------------- scratch (no allocations allowed) ----------------
__device__ float g_deg_inv[N_NODES];
__device__ int   g_deg[N_NODES];
__device__ float g_agg[NF];          // aggregation buffer (layers 2,3)
__device__ float g_h1[NF];           // layer-1 output
__device__ float g_h2[NF];           // layer-2 output
__device__ float g_agg3[N_NODES * 3];

// ---------------- degree + layer-1 aggregation ----------------
__global__ void k_zero_deg_agg3() {
    int i = blockIdx.x * blockDim.x + threadIdx.x;
    if (i < N_NODES) {
        g_deg[i] = 0;
        g_agg3[3 * i + 0] = 0.f;
        g_agg3[3 * i + 1] = 0.f;
        g_agg3[3 * i + 2] = 0.f;
    }
}

__global__ void k_deg_scatter3(const float* __restrict__ x,
                               const int* __restrict__ src,
                               const int* __restrict__ dst) {
    int e = blockIdx.x * blockDim.x + threadIdx.x;
    if (e < N_EDGES) {
        int s = __ldg(&src[e]);
        int d = __ldg(&dst[e]);
        float x0 = __ldg(&x[3 * s + 0]);
        float x1 = __ldg(&x[3 * s + 1]);
        float x2 = __ldg(&x[3 * s + 2]);
        atomicAdd(&g_deg[d], 1);
        atomicAdd(&g_agg3[3 * d + 0], x0);
        atomicAdd(&g_agg3[3 * d + 1], x1);
        atomicAdd(&g_agg3[3 * d + 2], x2);
    }
}

// layer 1 (fused): compute+store deg_inv, out=relu((agg3*deginv)@W1l + x@W1r + b1),
// and zero this node's g_agg row for the upcoming scatter.
__global__ void k_layer1(const float* __restrict__ x,
                         const float* __restrict__ W1l,
                         const float* __restrict__ W1r,
                         const float* __restrict__ b1) {
    __shared__ float wl[3 * CH], wr[3 * CH], bs[CH];
    int c = threadIdx.x;  // 0..127
    wl[c]       = W1l[c];
    wl[c + 128] = W1l[c + 128];
    wl[c + 256] = W1l[c + 256];
    wr[c]       = W1r[c];
    wr[c + 128] = W1r[c + 128];
    wr[c + 256] = W1r[c + 256];
    bs[c]       = b1[c];
    __syncthreads();
    for (int n = blockIdx.x; n < N_NODES; n += gridDim.x) {
        int dgi = g_deg[n];
        float s = dgi > 0 ? 1.0f / (float)dgi : 0.0f;
        if (c == 0) g_deg_inv[n] = s;
        float a0 = g_agg3[3 * n + 0] * s;
        float a1 = g_agg3[3 * n + 1] * s;
        float a2 = g_agg3[3 * n + 2] * s;
        float x0 = __ldg(&x[3 * n + 0]);
        float x1 = __ldg(&x[3 * n + 1]);
        float x2 = __ldg(&x[3 * n + 2]);
        float v = a0 * wl[c] + a1 * wl[c + 128] + a2 * wl[c + 256]
                + x0 * wr[c] + x1 * wr[c + 128] + x2 * wr[c + 256] + bs[c];
        g_h1[(size_t)n * CH + c] = fmaxf(v, 0.f);
        g_agg[(size_t)n * CH + c] = 0.f;   // folded zero_agg
    }
}

// ---------------- 128-wide aggregation ----------------
// one warp per edge; each lane moves one float4 (128 ch = 32 lanes * 4)
__global__ void k_scatter(int insel,
                          const int* __restrict__ src,
                          const int* __restrict__ dst) {
    const float* __restrict__ hin = insel ? g_h2 : g_h1;
    int idx = blockIdx.x * blockDim.x + threadIdx.x;
    int e = idx >> 5;
    int c = (idx & 31) << 2;
    if (e < N_EDGES) {
        int s = __ldg(&src[e]);
        int d = __ldg(&dst[e]);
        float4 v = *reinterpret_cast<const float4*>(hin + (size_t)s * CH + c);
        float* p = g_agg + (size_t)d * CH + c;
        asm volatile("red.global.add.v4.f32 [%0], {%1, %2, %3, %4};"
                     :: "l"(p), "f"(v.x), "f"(v.y), "f"(v.z), "f"(v.w)
                     : "memory");
    }
}

// ---------------- tf32 tensor-core GEMM, double-buffered ----------------
// out = relu(deginv*(agg@Wl) + hin@Wr + b); then zero this block's g_agg slice.
// BM=128, BN=128, BK=16, 2-stage smem, 1 sync/chunk, 256 threads, warp 32x64.
__device__ __forceinline__ uint32_t f2tf32(float f) {
    uint32_t u;
    asm("cvt.rna.tf32.f32 %0, %1;" : "=r"(u) : "f"(f));
    return u;
}

#define APW 20    // As pitch: 16 k-words + 4 pad (conflict-free frag loads)
#define BPW 132   // Bs pitch: 128 n-words + 4 pad

__global__ __launch_bounds__(256, 2) void k_gemm_tc(int insel, int outsel,
                                                    const float* __restrict__ Wl,
                                                    const float* __restrict__ Wr,
                                                    const float* __restrict__ bias,
                                                    float* __restrict__ extout) {
    const float* __restrict__ hin = insel ? g_h2 : g_h1;
    float* __restrict__ out = outsel ? extout : g_h2;

    __shared__ uint32_t As[2][128 * APW];   // [m:128][k:16] per stage
    __shared__ uint32_t Bs[2][16 * BPW];    // [k:16][n:128] per stage

    const int tid  = threadIdx.x;
    const int wid  = tid >> 5;
    const int lane = tid & 31;
    const int warp_m = wid >> 1;      // 0..3
    const int warp_n = wid & 1;       // 0..1
    const int tg  = lane >> 2;        // 0..7
    const int tig = lane & 3;         // 0..3

    const int block_m = blockIdx.x * 128;

    // A loader: 2 passes of (64 rows x 16 cols), one float4 each
    const int al   = tid >> 2;          // 0..63
    const int acol = (tid & 3) << 2;    // 0,4,8,12
    int arow0 = block_m + al;       if (arow0 >= N_NODES) arow0 = N_NODES - 1;
    int arow1 = block_m + al + 64;  if (arow1 >= N_NODES) arow1 = N_NODES - 1;
    // B loader: 2 passes of (8 k-rows x 128 cols), one float4 each
    const int brow = tid >> 5;          // 0..7 (+8 second pass)
    const int bcol = (tid & 31) << 2;   // 0..124

    // per-row deg scales, applied to accumulators between phases
    int rs = block_m + warp_m * 32 + tg;
    int r0c = rs      < N_NODES ? rs      : N_NODES - 1;
    int r1c = rs + 8  < N_NODES ? rs + 8  : N_NODES - 1;
    int r2c = rs + 16 < N_NODES ? rs + 16 : N_NODES - 1;
    int r3c = rs + 24 < N_NODES ? rs + 24 : N_NODES - 1;
    float ds0 = g_deg_inv[r0c];
    float ds1 = g_deg_inv[r1c];
    float ds2 = g_deg_inv[r2c];
    float ds3 = g_deg_inv[r3c];

    float acc[2][8][4];
#pragma unroll
    for (int mt = 0; mt < 2; ++mt)
#pragma unroll
        for (int nt = 0; nt < 8; ++nt)
#pragma unroll
            for (int i = 0; i < 4; ++i) acc[mt][nt][i] = 0.f;

    const float* Aptr0 = g_agg;  const float* Aptr1 = hin;
    const float* Bptr0 = Wl;     const float* Bptr1 = Wr;

    float4 a0v, a1v, b0v, b1v;
    // prologue: load + store chunk 0 (phase 0, k0 = 0)
    a0v = *reinterpret_cast<const float4*>(&Aptr0[(size_t)arow0 * 128 + acol]);
    a1v = *reinterpret_cast<const float4*>(&Aptr0[(size_t)arow1 * 128 + acol]);
    b0v = *reinterpret_cast<const float4*>(&Bptr0[(size_t)brow * 128 + bcol]);
    b1v = *reinterpret_cast<const float4*>(&Bptr0[(size_t)(brow + 8) * 128 + bcol]);
    {
        int ao0 = al * APW + acol, ao1 = (al + 64) * APW + acol;
        As[0][ao0 + 0] = f2tf32(a0v.x); As[0][ao0 + 1] = f2tf32(a0v.y);
        As[0][ao0 + 2] = f2tf32(a0v.z); As[0][ao0 + 3] = f2tf32(a0v.w);
        As[0][ao1 + 0] = f2tf32(a1v.x); As[0][ao1 + 1] = f2tf32(a1v.y);
        As[0][ao1 + 2] = f2tf32(a1v.z); As[0][ao1 + 3] = f2tf32(a1v.w);
        int bo0 = brow * BPW + bcol, bo1 = (brow + 8) * BPW + bcol;
        Bs[0][bo0 + 0] = f2tf32(b0v.x); Bs[0][bo0 + 1] = f2tf32(b0v.y);
        Bs[0][bo0 + 2] = f2tf32(b0v.z); Bs[0][bo0 + 3] = f2tf32(b0v.w);
        Bs[0][bo1 + 0] = f2tf32(b1v.x); Bs[0][bo1 + 1] = f2tf32(b1v.y);
        Bs[0][bo1 + 2] = f2tf32(b1v.z); Bs[0][bo1 + 3] = f2tf32(b1v.w);
    }
    __syncthreads();

#pragma unroll 1
    for (int ck = 0; ck < 16; ++ck) {
        const int s = ck & 1;
        // issue next chunk's global loads first (overlap with mma)
        if (ck < 15) {
            int cn = ck + 1;
            const float* A = (cn >> 3) ? Aptr1 : Aptr0;
            const float* B = (cn >> 3) ? Bptr1 : Bptr0;
            int k0 = (cn & 7) * 16;
            a0v = *reinterpret_cast<const float4*>(&A[(size_t)arow0 * 128 + k0 + acol]);
            a1v = *reinterpret_cast<const float4*>(&A[(size_t)arow1 * 128 + k0 + acol]);
            b0v = *reinterpret_cast<const float4*>(&B[(size_t)(k0 + brow) * 128 + bcol]);
            b1v = *reinterpret_cast<const float4*>(&B[(size_t)(k0 + brow + 8) * 128 + bcol]);
        }
        // mma on stage s: 2 k8 steps
#pragma unroll
        for (int ks = 0; ks < 2; ++ks) {
            const int kb = ks * 8;
            uint32_t a[2][4];
#pragma unroll
            for (int mt = 0; mt < 2; ++mt) {
                int r = warp_m * 32 + mt * 16;
                a[mt][0] = As[s][(r + tg)     * APW + kb + tig];
                a[mt][1] = As[s][(r + tg + 8) * APW + kb + tig];
                a[mt][2] = As[s][(r + tg)     * APW + kb + tig + 4];
                a[mt][3] = As[s][(r + tg + 8) * APW + kb + tig + 4];
            }
#pragma unroll
            for (int nt = 0; nt < 8; ++nt) {
                int cc = warp_n * 64 + nt * 8 + tg;
                uint32_t b0 = Bs[s][(kb + tig)     * BPW + cc];
                uint32_t b1 = Bs[s][(kb + tig + 4) * BPW + cc];
#pragma unroll
                for (int mt = 0; mt < 2; ++mt) {
                    asm volatile(
                        "mma.sync.aligned.m16n8k8.row.col.f32.tf32.tf32.f32 "
                        "{%0,%1,%2,%3}, {%4,%5,%6,%7}, {%8,%9}, {%0,%1,%2,%3};"
                        : "+f"(acc[mt][nt][0]), "+f"(acc[mt][nt][1]),
                          "+f"(acc[mt][nt][2]), "+f"(acc[mt][nt][3])
                        : "r"(a[mt][0]), "r"(a[mt][1]), "r"(a[mt][2]), "r"(a[mt][3]),
                          "r"(b0), "r"(b1));
                }
            }
        }
        // end of phase 0: scale accumulators by deg_inv (row-wise)
        if (ck == 7) {
#pragma unroll
            for (int nt = 0; nt < 8; ++nt) {
                acc[0][nt][0] *= ds0; acc[0][nt][1] *= ds0;
                acc[0][nt][2] *= ds1; acc[0][nt][3] *= ds1;
                acc[1][nt][0] *= ds2; acc[1][nt][1] *= ds2;
                acc[1][nt][2] *= ds3; acc[1][nt][3] *= ds3;
            }
        }
        // store next chunk into the other stage
        if (ck < 15) {
            const int sn = s ^ 1;
            int ao0 = al * APW + acol, ao1 = (al + 64) * APW + acol;
            As[sn][ao0 + 0] = f2tf32(a0v.x); As[sn][ao0 + 1] = f2tf32(a0v.y);
            As[sn][ao0 + 2] = f2tf32(a0v.z); As[sn][ao0 + 3] = f2tf32(a0v.w);
            As[sn][ao1 + 0] = f2tf32(a1v.x); As[sn][ao1 + 1] = f2tf32(a1v.y);
            As[sn][ao1 + 2] = f2tf32(a1v.z); As[sn][ao1 + 3] = f2tf32(a1v.w);
            int bo0 = brow * BPW + bcol, bo1 = (brow + 8) * BPW + bcol;
            Bs[sn][bo0 + 0] = f2tf32(b0v.x); Bs[sn][bo0 + 1] = f2tf32(b0v.y);
            Bs[sn][bo0 + 2] = f2tf32(b0v.z); Bs[sn][bo0 + 3] = f2tf32(b0v.w);
            Bs[sn][bo1 + 0] = f2tf32(b1v.x); Bs[sn][bo1 + 1] = f2tf32(b1v.y);
            Bs[sn][bo1 + 2] = f2tf32(b1v.z); Bs[sn][bo1 + 3] = f2tf32(b1v.w);
        }
        __syncthreads();
    }

    // epilogue: + bias, relu, store (float2 per row-fragment)
#pragma unroll
    for (int mt = 0; mt < 2; ++mt) {
        int r0 = block_m + warp_m * 32 + mt * 16 + tg;
        int r1 = r0 + 8;
#pragma unroll
        for (int nt = 0; nt < 8; ++nt) {
            int c = warp_n * 64 + nt * 8 + 2 * tig;
            float bb0 = __ldg(&bias[c]);
            float bb1 = __ldg(&bias[c + 1]);
            if (r0 < N_NODES) {
                float2 o;
                o.x = fmaxf(acc[mt][nt][0] + bb0, 0.f);
                o.y = fmaxf(acc[mt][nt][1] + bb1, 0.f);
                *reinterpret_cast<float2*>(&out[(size_t)r0 * 128 + c]) = o;
            }
            if (r1 < N_NODES) {
                float2 o;
                o.x = fmaxf(acc[mt][nt][2] + bb0, 0.f);
                o.y = fmaxf(acc[mt][nt][3] + bb1, 0.f);
                *reinterpret_cast<float2*>(&out[(size_t)r1 * 128 + c]) = o;
            }
        }
    }

    // zero this block's g_agg slice for the next aggregation pass
    {
        int zr = block_m + (tid >> 1);
        if (zr < N_NODES) {
            float4* p = reinterpret_cast<float4*>(g_agg + (size_t)zr * 128 + (tid & 1) * 64);
#pragma unroll
            for (int i = 0; i < 16; ++i) p[i] = make_float4(0.f, 0.f, 0.f, 0.f);
        }
    }
}

// ---------------- launch ----------------
extern "C" void kernel_launch(void* const* d_in, const int* in_sizes, int n_in,
                              void* d_out, int out_size) {
    const float* x   = (const float*)d_in[0];
    const int*   ei  = (const int*)d_in[1];
    const float* W1l = (const float*)d_in[2];
    const float* W1r = (const float*)d_in[3];
    const float* b1  = (const float*)d_in[4];
    const float* W2l = (const float*)d_in[5];
    const float* W2r = (const float*)d_in[6];
    const float* b2  = (const float*)d_in[7];
    const float* W3l = (const float*)d_in[8];
    const float* W3r = (const float*)d_in[9];
    const float* b3  = (const float*)d_in[10];
    float* out = (float*)d_out;

    const int* src = ei;
    const int* dst = ei + N_EDGES;

    const int TB = 256;
    const int grid_nodes = (N_NODES + TB - 1) / TB;
    const int grid_edges = (N_EDGES + TB - 1) / TB;
    const int grid_scat  = (N_EDGES * 32 + TB - 1) / TB;
    const int gemm_blocks = (N_NODES + 127) / 128;

    // degree + layer-1 aggregation (3-dim space, before the linear: linearity)
    k_zero_deg_agg3<<<grid_nodes, TB>>>();
    k_deg_scatter3<<<grid_edges, TB>>>(x, src, dst);
    k_layer1<<<2048, 128>>>(x, W1l, W1r, b1);   // -> g_h1, g_deg_inv, zeroes g_agg

    // layer 2: g_h1 -> g_h2
    k_scatter<<<grid_scat, TB>>>(0, src, dst);
    k_gemm_tc<<<gemm_blocks, 256>>>(0, 0, W2l, W2r, b2, out);

    // layer 3: g_h2 -> out (g_agg re-zeroed by previous gemm epilogue)
    k_scatter<<<grid_scat, TB>>>(1, src, dst);
    k_gemm_tc<<<gemm_blocks, 256>>>(1, 1, W3l, W3r, b3, out);
}